// round 8
// baseline (speedup 1.0000x reference)
#include <cuda_runtime.h>
#include <cuda_fp16.h>
#include <cstdint>

#define N_NODES 100000
#define N_EDGES 1600000
#define F_IN    128
#define F_HID   64
#define F_OUT   40

#define CHUNK0  50048                     // multiple of 128 and 32
#define CHUNK1  (N_NODES - CHUNK0)

#define SCAN_T  1024
#define SCAN_NB ((N_NODES + SCAN_T - 1) / SCAN_T)   // 98

// ---------------- scratch (static device globals; no allocation) ----------------
__device__ int    g_degs_i[N_NODES];
__device__ int    g_degd_i[N_NODES];
__device__ float  g_ns[N_NODES];
__device__ float  g_nd[N_NODES];
__device__ int    g_incl[N_NODES];
__device__ int    g_rowoff[N_NODES + 1];
__device__ int    g_cursor[N_NODES];
__device__ int    g_partial[SCAN_NB];
__device__ int    g_csrc[N_EDGES];
__device__ __half g_xw64[(size_t)N_NODES * F_HID];
__device__ __half g_xw40[(size_t)N_NODES * F_OUT];
__device__ __half g_agg [(size_t)N_NODES * F_HID];

// ---------------- zero both degree arrays (int4) ----------------
__global__ void k_zero_deg() {
    int i = blockIdx.x * blockDim.x + threadIdx.x;
    if (i < N_NODES / 4) {
        ((int4*)g_degs_i)[i] = make_int4(0, 0, 0, 0);
        ((int4*)g_degd_i)[i] = make_int4(0, 0, 0, 0);
    }
}

// ---------------- degree histograms (4 edges per thread) ----------------
__global__ void k_deg_dst(const int* __restrict__ dst) {
    int i = blockIdx.x * blockDim.x + threadIdx.x;
    if (i < N_EDGES / 4) {
        const int4 d = __ldg(&((const int4*)dst)[i]);
        atomicAdd(&g_degd_i[d.x], 1);
        atomicAdd(&g_degd_i[d.y], 1);
        atomicAdd(&g_degd_i[d.z], 1);
        atomicAdd(&g_degd_i[d.w], 1);
    }
}

__global__ void k_deg_src(const int* __restrict__ src) {
    int i = blockIdx.x * blockDim.x + threadIdx.x;
    if (i < N_EDGES / 4) {
        const int4 s = __ldg(&((const int4*)src)[i]);
        atomicAdd(&g_degs_i[s.x], 1);
        atomicAdd(&g_degs_i[s.y], 1);
        atomicAdd(&g_degs_i[s.z], 1);
        atomicAdd(&g_degs_i[s.w], 1);
    }
}

__global__ void k_ns() {
    int i = blockIdx.x * blockDim.x + threadIdx.x;
    if (i < N_NODES) g_ns[i] = rsqrtf(fmaxf((float)g_degs_i[i], 1.0f));
}

// ---------------- CSR build ----------------
__global__ __launch_bounds__(SCAN_T) void k_scan_block() {
    __shared__ int ws[32];
    int g = blockIdx.x * SCAN_T + threadIdx.x;
    int lane = threadIdx.x & 31, wid = threadIdx.x >> 5;
    int x = (g < N_NODES) ? g_degd_i[g] : 0;
#pragma unroll
    for (int o = 1; o < 32; o <<= 1) {
        int y = __shfl_up_sync(0xFFFFFFFFu, x, o);
        if (lane >= o) x += y;
    }
    if (lane == 31) ws[wid] = x;
    __syncthreads();
    if (wid == 0) {
        int y = ws[lane];
#pragma unroll
        for (int o = 1; o < 32; o <<= 1) {
            int z = __shfl_up_sync(0xFFFFFFFFu, y, o);
            if (lane >= o) y += z;
        }
        ws[lane] = y;
    }
    __syncthreads();
    int incl = x + (wid > 0 ? ws[wid - 1] : 0);
    if (g < N_NODES) g_incl[g] = incl;
    if (threadIdx.x == SCAN_T - 1) g_partial[blockIdx.x] = incl;
}

__global__ __launch_bounds__(SCAN_T) void k_finalize() {
    __shared__ int ws[32];
    __shared__ int s_off;
    const int tid = threadIdx.x;
    const int lane = tid & 31, w = tid >> 5;

    int v = 0;
    if (tid < SCAN_NB && tid < blockIdx.x) v = g_partial[tid];
#pragma unroll
    for (int o = 16; o > 0; o >>= 1) v += __shfl_down_sync(0xFFFFFFFFu, v, o);
    if (tid < 128 && lane == 0) ws[w] = v;
    __syncthreads();
    if (tid == 0) s_off = ws[0] + ws[1] + ws[2] + ws[3];
    __syncthreads();
    const int off = s_off;

    int g = blockIdx.x * SCAN_T + tid;
    if (g < N_NODES) {
        int dd   = g_degd_i[g];
        int incl = g_incl[g] + off;
        g_rowoff[g + 1] = incl;
        g_cursor[g] = incl - dd;
        if (g == 0) g_rowoff[0] = 0;
        g_nd[g] = rsqrtf(fmaxf((float)dd, 1.0f));
    }
}

__global__ void k_fill(const int* __restrict__ src, const int* __restrict__ dst) {
    int i = blockIdx.x * blockDim.x + threadIdx.x;
    if (i < N_EDGES / 4) {
        const int4 s = __ldg(&((const int4*)src)[i]);
        const int4 d = __ldg(&((const int4*)dst)[i]);
        g_csrc[atomicAdd(&g_cursor[d.x], 1)] = s.x;
        g_csrc[atomicAdd(&g_cursor[d.y], 1)] = s.y;
        g_csrc[atomicAdd(&g_cursor[d.z], 1)] = s.z;
        g_csrc[atomicAdd(&g_cursor[d.w], 1)] = s.w;
    }
}

// ---------------- typed quad loader for GEMM X tiles ----------------
__device__ __forceinline__ float4 load_quad(const float* p) {
    return *(const float4*)p;
}
__device__ __forceinline__ float4 load_quad(const __half* p) {
    union { uint2 u; __half2 h[2]; } r;
    r.u = *(const uint2*)p;
    const float2 a = __half22float2(r.h[0]);
    const float2 b = __half22float2(r.h[1]);
    return make_float4(a.x, a.y, b.x, b.y);
}

// ---------------- tiled fp32 GEMM -> fp16, row range [rowBase, rowEnd) ----------------
template <int K, int M, bool PRE, bool SNS, typename TX>
__global__ __launch_bounds__(256) void k_gemm(const TX* __restrict__ X,
                                              const float* __restrict__ W,
                                              __half* __restrict__ Y,
                                              const float* __restrict__ bpre,
                                              int rowBase, int rowEnd) {
    __shared__ __align__(16) float Xs[16][132];
    __shared__ __align__(16) float Ws[16][64];

    const int tid  = threadIdx.x;
    const int tx   = tid & 15;
    const int ty   = tid >> 4;
    const int row0 = rowBase + blockIdx.x * 128;

    const int lr   = tid >> 1;
    const int lq   = tid & 1;
    const int lrow = row0 + lr;
    const bool lok = (lrow < rowEnd);

    float ndv = 1.0f;
    if (PRE) ndv = lok ? g_nd[lrow] : 0.0f;

    float acc[8][4];
#pragma unroll
    for (int i = 0; i < 8; i++)
#pragma unroll
        for (int j = 0; j < 4; j++) acc[i][j] = 0.0f;

    for (int kc = 0; kc < K; kc += 16) {
#pragma unroll
        for (int q = 0; q < 2; q++) {
            const int kq = lq + q * 2;
            float4 xv = make_float4(0.f, 0.f, 0.f, 0.f);
            if (lok)
                xv = load_quad(&X[(size_t)lrow * K + kc + kq * 4]);
            if (PRE) {
                xv.x = fmaxf(fmaf(xv.x, ndv, __ldg(&bpre[kc + kq * 4 + 0])), 0.f);
                xv.y = fmaxf(fmaf(xv.y, ndv, __ldg(&bpre[kc + kq * 4 + 1])), 0.f);
                xv.z = fmaxf(fmaf(xv.z, ndv, __ldg(&bpre[kc + kq * 4 + 2])), 0.f);
                xv.w = fmaxf(fmaf(xv.w, ndv, __ldg(&bpre[kc + kq * 4 + 3])), 0.f);
            }
            Xs[kq * 4 + 0][lr] = xv.x;
            Xs[kq * 4 + 1][lr] = xv.y;
            Xs[kq * 4 + 2][lr] = xv.z;
            Xs[kq * 4 + 3][lr] = xv.w;
        }
        {
            const int wk = tid >> 4;
            const int wc = (tid & 15) * 4;
            float4 wv = make_float4(0.f, 0.f, 0.f, 0.f);
            if (wc < M)
                wv = *(const float4*)&W[(size_t)(kc + wk) * M + wc];
            *(float4*)&Ws[wk][wc] = wv;
        }
        __syncthreads();

#pragma unroll
        for (int k = 0; k < 16; k++) {
            const float4 b  = *(const float4*)&Ws[k][tx * 4];
            const float4 a0 = *(const float4*)&Xs[k][ty * 8];
            const float4 a1 = *(const float4*)&Xs[k][ty * 8 + 4];
            acc[0][0] += a0.x * b.x; acc[0][1] += a0.x * b.y; acc[0][2] += a0.x * b.z; acc[0][3] += a0.x * b.w;
            acc[1][0] += a0.y * b.x; acc[1][1] += a0.y * b.y; acc[1][2] += a0.y * b.z; acc[1][3] += a0.y * b.w;
            acc[2][0] += a0.z * b.x; acc[2][1] += a0.z * b.y; acc[2][2] += a0.z * b.z; acc[2][3] += a0.z * b.w;
            acc[3][0] += a0.w * b.x; acc[3][1] += a0.w * b.y; acc[3][2] += a0.w * b.z; acc[3][3] += a0.w * b.w;
            acc[4][0] += a1.x * b.x; acc[4][1] += a1.x * b.y; acc[4][2] += a1.x * b.z; acc[4][3] += a1.x * b.w;
            acc[5][0] += a1.y * b.x; acc[5][1] += a1.y * b.y; acc[5][2] += a1.y * b.z; acc[5][3] += a1.y * b.w;
            acc[6][0] += a1.z * b.x; acc[6][1] += a1.z * b.y; acc[6][2] += a1.z * b.z; acc[6][3] += a1.z * b.w;
            acc[7][0] += a1.w * b.x; acc[7][1] += a1.w * b.y; acc[7][2] += a1.w * b.z; acc[7][3] += a1.w * b.w;
        }
        __syncthreads();
    }

    const int c = tx * 4;
#pragma unroll
    for (int i = 0; i < 8; i++) {
        const int rr = row0 + ty * 8 + i;
        if (rr < rowEnd && c < M) {
            const float s = SNS ? g_ns[rr] : 1.0f;
            union { uint2 u; __half2 h[2]; } p;
            p.h[0] = __floats2half2_rn(acc[i][0] * s, acc[i][1] * s);
            p.h[1] = __floats2half2_rn(acc[i][2] * s, acc[i][3] * s);
            *(uint2*)&Y[(size_t)rr * M + c] = p.u;
        }
    }
}

// ---------------- CSR gather (fp16 in/out, fp32 accum): 8 thr/node, 16B loads ----------------
__device__ __forceinline__ void h8_acc(float* acc, uint4 raw, float n) {
    union { uint4 u; __half2 h[4]; } p; p.u = raw;
#pragma unroll
    for (int j = 0; j < 4; j++) {
        const float2 v = __half22float2(p.h[j]);
        acc[2 * j + 0] = fmaf(v.x, n, acc[2 * j + 0]);
        acc[2 * j + 1] = fmaf(v.y, n, acc[2 * j + 1]);
    }
}

template <bool ESCALE>
__global__ __launch_bounds__(256) void k_gather64(const __half* __restrict__ xw,
                                                  __half* __restrict__ agg,
                                                  int nodeBase, int nodeEnd) {
    const int node = nodeBase + blockIdx.x * 32 + (threadIdx.x >> 3);
    if (node >= nodeEnd) return;
    const int f   = (threadIdx.x & 7) << 3;
    int       i   = g_rowoff[node];
    const int end = g_rowoff[node + 1];
    float acc[8] = {0.f, 0.f, 0.f, 0.f, 0.f, 0.f, 0.f, 0.f};

    for (; i + 3 < end; i += 4) {
        const int s0 = __ldg(&g_csrc[i + 0]);
        const int s1 = __ldg(&g_csrc[i + 1]);
        const int s2 = __ldg(&g_csrc[i + 2]);
        const int s3 = __ldg(&g_csrc[i + 3]);
        float n0 = 1.f, n1 = 1.f, n2 = 1.f, n3 = 1.f;
        if (ESCALE) {
            n0 = __ldg(&g_ns[s0]); n1 = __ldg(&g_ns[s1]);
            n2 = __ldg(&g_ns[s2]); n3 = __ldg(&g_ns[s3]);
        }
        const uint4 r0 = __ldg((const uint4*)&xw[(size_t)s0 * 64 + f]);
        const uint4 r1 = __ldg((const uint4*)&xw[(size_t)s1 * 64 + f]);
        const uint4 r2 = __ldg((const uint4*)&xw[(size_t)s2 * 64 + f]);
        const uint4 r3 = __ldg((const uint4*)&xw[(size_t)s3 * 64 + f]);
        h8_acc(acc, r0, n0); h8_acc(acc, r1, n1);
        h8_acc(acc, r2, n2); h8_acc(acc, r3, n3);
    }
    for (; i < end; i++) {
        const int s = __ldg(&g_csrc[i]);
        const float n = ESCALE ? __ldg(&g_ns[s]) : 1.0f;
        h8_acc(acc, __ldg((const uint4*)&xw[(size_t)s * 64 + f]), n);
    }

    union { uint4 u; __half2 h[4]; } o;
    o.h[0] = __floats2half2_rn(acc[0], acc[1]);
    o.h[1] = __floats2half2_rn(acc[2], acc[3]);
    o.h[2] = __floats2half2_rn(acc[4], acc[5]);
    o.h[3] = __floats2half2_rn(acc[6], acc[7]);
    *(uint4*)&agg[(size_t)node * 64 + f] = o.u;
}

// 40-wide fp16 gather with fused final epilogue (fp32 output)
__device__ __forceinline__ void h4_acc(float4& acc, uint2 raw) {
    union { uint2 u; __half2 h[2]; } p; p.u = raw;
    const float2 a = __half22float2(p.h[0]);
    const float2 b = __half22float2(p.h[1]);
    acc.x += a.x; acc.y += a.y; acc.z += b.x; acc.w += b.y;
}

__global__ __launch_bounds__(256) void k_gather40(const __half* __restrict__ xw,
                                                  float* __restrict__ out,
                                                  const float* __restrict__ b2) {
    const int node = blockIdx.x * 16 + (threadIdx.x >> 4);
    if (node >= N_NODES) return;
    const int f = (threadIdx.x & 15) << 2;
    if (f >= F_OUT) return;
    int       i   = g_rowoff[node];
    const int end = g_rowoff[node + 1];
    float4 acc = make_float4(0.f, 0.f, 0.f, 0.f);
    for (; i + 3 < end; i += 4) {
        const int s0 = __ldg(&g_csrc[i + 0]);
        const int s1 = __ldg(&g_csrc[i + 1]);
        const int s2 = __ldg(&g_csrc[i + 2]);
        const int s3 = __ldg(&g_csrc[i + 3]);
        h4_acc(acc, __ldg((const uint2*)&xw[(size_t)s0 * F_OUT + f]));
        h4_acc(acc, __ldg((const uint2*)&xw[(size_t)s1 * F_OUT + f]));
        h4_acc(acc, __ldg((const uint2*)&xw[(size_t)s2 * F_OUT + f]));
        h4_acc(acc, __ldg((const uint2*)&xw[(size_t)s3 * F_OUT + f]));
    }
    for (; i < end; i++) {
        const int s = __ldg(&g_csrc[i]);
        h4_acc(acc, __ldg((const uint2*)&xw[(size_t)s * F_OUT + f]));
    }
    const float nd = g_nd[node];
    float4 o;
    o.x = fmaf(acc.x, nd, __ldg(&b2[f + 0]));
    o.y = fmaf(acc.y, nd, __ldg(&b2[f + 1]));
    o.z = fmaf(acc.z, nd, __ldg(&b2[f + 2]));
    o.w = fmaf(acc.w, nd, __ldg(&b2[f + 3]));
    *(float4*)&out[(size_t)node * F_OUT + f] = o;
}

// ---------------- host launch ----------------
extern "C" void kernel_launch(void* const* d_in, const int* in_sizes, int n_in,
                              void* d_out, int out_size) {
    (void)in_sizes; (void)n_in; (void)out_size;
    const float* h   = (const float*)d_in[0];
    const float* W0  = (const float*)d_in[1];
    const float* b0  = (const float*)d_in[2];
    const float* W1  = (const float*)d_in[3];
    const float* b1  = (const float*)d_in[4];
    const float* W2  = (const float*)d_in[5];
    const float* b2  = (const float*)d_in[6];
    const int*   src = (const int*)d_in[7];
    const int*   dst = (const int*)d_in[8];
    float* out = (float*)d_out;

    __half *pXW64, *pXW40, *pAgg;
    cudaGetSymbolAddress((void**)&pXW64, g_xw64);
    cudaGetSymbolAddress((void**)&pXW40, g_xw40);
    cudaGetSymbolAddress((void**)&pAgg,  g_agg);

    static cudaStream_t s2 = []() {
        cudaStream_t s; cudaStreamCreateWithFlags(&s, cudaStreamNonBlocking); return s;
    }();
    auto mkev = []() {
        cudaEvent_t e; cudaEventCreateWithFlags(&e, cudaEventDisableTiming); return e;
    };
    static cudaEvent_t evFork = mkev();
    static cudaEvent_t evJoin = mkev();
    static cudaEvent_t evA0 = mkev(), evA1 = mkev();
    static cudaEvent_t evG1 = mkev();
    static cudaEvent_t evB0 = mkev(), evB1 = mkev();
    static cudaEvent_t evG2 = mkev();

    const int nodeBlocks  = (N_NODES + 255) / 256;
    const int edge4Blocks = (N_EDGES / 4 + 255) / 256;
    const int gemmBlocksAll = (N_NODES + 127) / 128;
    const int gemmBlocksC0  = CHUNK0 / 128;
    const int gemmBlocksC1  = (CHUNK1 + 127) / 128;
    const int gathBlocksC0  = CHUNK0 / 32;
    const int gathBlocksC1  = (CHUNK1 + 31) / 32;
    const int gath40Blocks  = (N_NODES + 15) / 16;

    // ---- main: zero degrees, then fork ----
    k_zero_deg<<<(N_NODES / 4 + 255) / 256, 256>>>();
    cudaEventRecord(evFork, 0);

    // ---- side stream: GEMM0 (all rows) + src-degree histogram + ns ----
    cudaStreamWaitEvent(s2, evFork, 0);
    k_gemm<F_IN, F_HID, false, false><<<gemmBlocksAll, 256, 0, s2>>>(h, W0, pXW64, b0, 0, N_NODES);
    k_deg_src<<<edge4Blocks, 256, 0, s2>>>(src);
    k_ns<<<nodeBlocks, 256, 0, s2>>>();
    cudaEventRecord(evJoin, s2);

    // ---- main: dst histogram + CSR ----
    k_deg_dst<<<edge4Blocks, 256>>>(dst);
    k_scan_block<<<SCAN_NB, SCAN_T>>>();
    k_finalize<<<SCAN_NB, SCAN_T>>>();
    k_fill<<<edge4Blocks, 256>>>(src, dst);

    // ---- join, layer-0 gather in 2 chunks (ns applied per edge) ----
    cudaStreamWaitEvent(0, evJoin, 0);
    k_gather64<true><<<gathBlocksC0, 256>>>(pXW64, pAgg, 0, CHUNK0);
    cudaEventRecord(evA0, 0);
    k_gather64<true><<<gathBlocksC1, 256>>>(pXW64, pAgg, CHUNK0, N_NODES);
    cudaEventRecord(evA1, 0);

    // ---- gemm1 chunks on s2, pipelined against gatherA ----
    cudaStreamWaitEvent(s2, evA0, 0);
    k_gemm<F_HID, F_HID, true, true><<<gemmBlocksC0, 256, 0, s2>>>(pAgg, W1, pXW64, b0, 0, CHUNK0);
    cudaStreamWaitEvent(s2, evA1, 0);
    k_gemm<F_HID, F_HID, true, true><<<gemmBlocksC1, 256, 0, s2>>>(pAgg, W1, pXW64, b0, CHUNK0, N_NODES);
    cudaEventRecord(evG1, s2);

    // ---- layer-1 gather in 2 chunks on main (needs all of gemm1) ----
    cudaStreamWaitEvent(0, evG1, 0);
    k_gather64<false><<<gathBlocksC0, 256>>>(pXW64, pAgg, 0, CHUNK0);
    cudaEventRecord(evB0, 0);
    k_gather64<false><<<gathBlocksC1, 256>>>(pXW64, pAgg, CHUNK0, N_NODES);
    cudaEventRecord(evB1, 0);

    // ---- gemm2 chunks on s2, pipelined against gatherB ----
    cudaStreamWaitEvent(s2, evB0, 0);
    k_gemm<F_HID, F_OUT, true, true><<<gemmBlocksC0, 256, 0, s2>>>(pAgg, W2, pXW40, b1, 0, CHUNK0);
    cudaStreamWaitEvent(s2, evB1, 0);
    k_gemm<F_HID, F_OUT, true, true><<<gemmBlocksC1, 256, 0, s2>>>(pAgg, W2, pXW40, b1, CHUNK0, N_NODES);
    cudaEventRecord(evG2, s2);

    // ---- final gather (+ fused bias/norm epilogue) on main ----
    cudaStreamWaitEvent(0, evG2, 0);
    k_gather40<<<gath40Blocks, 256>>>(pXW40, out, b2);
}

// round 9
// speedup vs baseline: 1.0749x; 1.0749x over previous
#include <cuda_runtime.h>
#include <cuda_fp16.h>
#include <cstdint>

#define N_NODES 100000
#define N_EDGES 1600000
#define F_IN    128
#define F_HID   64
#define F_OUT   40

#define SCAN_T  1024
#define SCAN_NB ((N_NODES + SCAN_T - 1) / SCAN_T)   // 98

// ---------------- scratch (static device globals; no allocation) ----------------
__device__ int    g_degs_i[N_NODES];
__device__ int    g_degd_i[N_NODES];
__device__ float  g_ns[N_NODES];
__device__ float  g_nd[N_NODES];
__device__ int    g_incl[N_NODES];
__device__ int    g_rowoff[N_NODES + 1];
__device__ int    g_cursor[N_NODES];
__device__ int    g_partial[SCAN_NB];
__device__ int    g_csrc[N_EDGES];
__device__ __half g_xw64[(size_t)N_NODES * F_HID];
__device__ __half g_xw40[(size_t)N_NODES * F_OUT];
__device__ __half g_agg [(size_t)N_NODES * F_HID];

// ---------------- zero both degree arrays (int4) ----------------
__global__ void k_zero_deg() {
    int i = blockIdx.x * blockDim.x + threadIdx.x;
    if (i < N_NODES / 4) {
        ((int4*)g_degs_i)[i] = make_int4(0, 0, 0, 0);
        ((int4*)g_degd_i)[i] = make_int4(0, 0, 0, 0);
    }
}

// ---------------- degree histograms (4 edges per thread) ----------------
__global__ void k_deg_dst(const int* __restrict__ dst) {
    int i = blockIdx.x * blockDim.x + threadIdx.x;
    if (i < N_EDGES / 4) {
        const int4 d = __ldg(&((const int4*)dst)[i]);
        atomicAdd(&g_degd_i[d.x], 1);
        atomicAdd(&g_degd_i[d.y], 1);
        atomicAdd(&g_degd_i[d.z], 1);
        atomicAdd(&g_degd_i[d.w], 1);
    }
}

__global__ void k_deg_src(const int* __restrict__ src) {
    int i = blockIdx.x * blockDim.x + threadIdx.x;
    if (i < N_EDGES / 4) {
        const int4 s = __ldg(&((const int4*)src)[i]);
        atomicAdd(&g_degs_i[s.x], 1);
        atomicAdd(&g_degs_i[s.y], 1);
        atomicAdd(&g_degs_i[s.z], 1);
        atomicAdd(&g_degs_i[s.w], 1);
    }
}

__global__ void k_ns() {
    int i = blockIdx.x * blockDim.x + threadIdx.x;
    if (i < N_NODES) g_ns[i] = rsqrtf(fmaxf((float)g_degs_i[i], 1.0f));
}

// ---------------- CSR build ----------------
__global__ __launch_bounds__(SCAN_T) void k_scan_block() {
    __shared__ int ws[32];
    int g = blockIdx.x * SCAN_T + threadIdx.x;
    int lane = threadIdx.x & 31, wid = threadIdx.x >> 5;
    int x = (g < N_NODES) ? g_degd_i[g] : 0;
#pragma unroll
    for (int o = 1; o < 32; o <<= 1) {
        int y = __shfl_up_sync(0xFFFFFFFFu, x, o);
        if (lane >= o) x += y;
    }
    if (lane == 31) ws[wid] = x;
    __syncthreads();
    if (wid == 0) {
        int y = ws[lane];
#pragma unroll
        for (int o = 1; o < 32; o <<= 1) {
            int z = __shfl_up_sync(0xFFFFFFFFu, y, o);
            if (lane >= o) y += z;
        }
        ws[lane] = y;
    }
    __syncthreads();
    int incl = x + (wid > 0 ? ws[wid - 1] : 0);
    if (g < N_NODES) g_incl[g] = incl;
    if (threadIdx.x == SCAN_T - 1) g_partial[blockIdx.x] = incl;
}

__global__ __launch_bounds__(SCAN_T) void k_finalize() {
    __shared__ int ws[32];
    __shared__ int s_off;
    const int tid = threadIdx.x;
    const int lane = tid & 31, w = tid >> 5;

    int v = 0;
    if (tid < SCAN_NB && tid < blockIdx.x) v = g_partial[tid];
#pragma unroll
    for (int o = 16; o > 0; o >>= 1) v += __shfl_down_sync(0xFFFFFFFFu, v, o);
    if (tid < 128 && lane == 0) ws[w] = v;
    __syncthreads();
    if (tid == 0) s_off = ws[0] + ws[1] + ws[2] + ws[3];
    __syncthreads();
    const int off = s_off;

    int g = blockIdx.x * SCAN_T + tid;
    if (g < N_NODES) {
        int dd   = g_degd_i[g];
        int incl = g_incl[g] + off;
        g_rowoff[g + 1] = incl;
        g_cursor[g] = incl - dd;
        if (g == 0) g_rowoff[0] = 0;
        g_nd[g] = rsqrtf(fmaxf((float)dd, 1.0f));
    }
}

__global__ void k_fill(const int* __restrict__ src, const int* __restrict__ dst) {
    int i = blockIdx.x * blockDim.x + threadIdx.x;
    if (i < N_EDGES / 4) {
        const int4 s = __ldg(&((const int4*)src)[i]);
        const int4 d = __ldg(&((const int4*)dst)[i]);
        g_csrc[atomicAdd(&g_cursor[d.x], 1)] = s.x;
        g_csrc[atomicAdd(&g_cursor[d.y], 1)] = s.y;
        g_csrc[atomicAdd(&g_cursor[d.z], 1)] = s.z;
        g_csrc[atomicAdd(&g_cursor[d.w], 1)] = s.w;
    }
}

// ---------------- typed quad loader for GEMM X tiles ----------------
__device__ __forceinline__ float4 load_quad(const float* p) {
    return *(const float4*)p;
}
__device__ __forceinline__ float4 load_quad(const __half* p) {
    union { uint2 u; __half2 h[2]; } r;
    r.u = *(const uint2*)p;
    const float2 a = __half22float2(r.h[0]);
    const float2 b = __half22float2(r.h[1]);
    return make_float4(a.x, a.y, b.x, b.y);
}

// ---------------- tiled fp32 GEMM -> fp16 output ----------------
// 128 rows x 64 cols, 256 threads, 8x4 microtile, K-chunks of 16.
// PRE: x' = relu(x * g_nd[row] + bpre[k]).  SNS: y = acc * g_ns[row].
template <int K, int M, bool PRE, bool SNS, typename TX>
__global__ __launch_bounds__(256) void k_gemm(const TX* __restrict__ X,
                                              const float* __restrict__ W,
                                              __half* __restrict__ Y,
                                              const float* __restrict__ bpre) {
    __shared__ __align__(16) float Xs[16][132];
    __shared__ __align__(16) float Ws[16][64];

    const int tid  = threadIdx.x;
    const int tx   = tid & 15;
    const int ty   = tid >> 4;
    const int row0 = blockIdx.x * 128;

    const int lr   = tid >> 1;
    const int lq   = tid & 1;
    const int lrow = row0 + lr;
    const bool lok = (lrow < N_NODES);

    float ndv = 1.0f;
    if (PRE) ndv = lok ? g_nd[lrow] : 0.0f;

    float acc[8][4];
#pragma unroll
    for (int i = 0; i < 8; i++)
#pragma unroll
        for (int j = 0; j < 4; j++) acc[i][j] = 0.0f;

    for (int kc = 0; kc < K; kc += 16) {
#pragma unroll
        for (int q = 0; q < 2; q++) {
            const int kq = lq + q * 2;
            float4 xv = make_float4(0.f, 0.f, 0.f, 0.f);
            if (lok)
                xv = load_quad(&X[(size_t)lrow * K + kc + kq * 4]);
            if (PRE) {
                xv.x = fmaxf(fmaf(xv.x, ndv, __ldg(&bpre[kc + kq * 4 + 0])), 0.f);
                xv.y = fmaxf(fmaf(xv.y, ndv, __ldg(&bpre[kc + kq * 4 + 1])), 0.f);
                xv.z = fmaxf(fmaf(xv.z, ndv, __ldg(&bpre[kc + kq * 4 + 2])), 0.f);
                xv.w = fmaxf(fmaf(xv.w, ndv, __ldg(&bpre[kc + kq * 4 + 3])), 0.f);
            }
            Xs[kq * 4 + 0][lr] = xv.x;
            Xs[kq * 4 + 1][lr] = xv.y;
            Xs[kq * 4 + 2][lr] = xv.z;
            Xs[kq * 4 + 3][lr] = xv.w;
        }
        {
            const int wk = tid >> 4;
            const int wc = (tid & 15) * 4;
            float4 wv = make_float4(0.f, 0.f, 0.f, 0.f);
            if (wc < M)
                wv = *(const float4*)&W[(size_t)(kc + wk) * M + wc];
            *(float4*)&Ws[wk][wc] = wv;
        }
        __syncthreads();

#pragma unroll
        for (int k = 0; k < 16; k++) {
            const float4 b  = *(const float4*)&Ws[k][tx * 4];
            const float4 a0 = *(const float4*)&Xs[k][ty * 8];
            const float4 a1 = *(const float4*)&Xs[k][ty * 8 + 4];
            acc[0][0] += a0.x * b.x; acc[0][1] += a0.x * b.y; acc[0][2] += a0.x * b.z; acc[0][3] += a0.x * b.w;
            acc[1][0] += a0.y * b.x; acc[1][1] += a0.y * b.y; acc[1][2] += a0.y * b.z; acc[1][3] += a0.y * b.w;
            acc[2][0] += a0.z * b.x; acc[2][1] += a0.z * b.y; acc[2][2] += a0.z * b.z; acc[2][3] += a0.z * b.w;
            acc[3][0] += a0.w * b.x; acc[3][1] += a0.w * b.y; acc[3][2] += a0.w * b.z; acc[3][3] += a0.w * b.w;
            acc[4][0] += a1.x * b.x; acc[4][1] += a1.x * b.y; acc[4][2] += a1.x * b.z; acc[4][3] += a1.x * b.w;
            acc[5][0] += a1.y * b.x; acc[5][1] += a1.y * b.y; acc[5][2] += a1.y * b.z; acc[5][3] += a1.y * b.w;
            acc[6][0] += a1.z * b.x; acc[6][1] += a1.z * b.y; acc[6][2] += a1.z * b.z; acc[6][3] += a1.z * b.w;
            acc[7][0] += a1.w * b.x; acc[7][1] += a1.w * b.y; acc[7][2] += a1.w * b.z; acc[7][3] += a1.w * b.w;
        }
        __syncthreads();
    }

    const int c = tx * 4;
#pragma unroll
    for (int i = 0; i < 8; i++) {
        const int rr = row0 + ty * 8 + i;
        if (rr < N_NODES && c < M) {
            const float s = SNS ? g_ns[rr] : 1.0f;
            union { uint2 u; __half2 h[2]; } p;
            p.h[0] = __floats2half2_rn(acc[i][0] * s, acc[i][1] * s);
            p.h[1] = __floats2half2_rn(acc[i][2] * s, acc[i][3] * s);
            *(uint2*)&Y[(size_t)rr * M + c] = p.u;
        }
    }
}

// ---------------- CSR gather (fp16 in/out, fp32 accum): 8 thr/node, 16B loads ----------------
__device__ __forceinline__ void h8_acc(float* acc, uint4 raw) {
    union { uint4 u; __half2 h[4]; } p; p.u = raw;
#pragma unroll
    for (int j = 0; j < 4; j++) {
        const float2 v = __half22float2(p.h[j]);
        acc[2 * j + 0] += v.x;
        acc[2 * j + 1] += v.y;
    }
}

__global__ __launch_bounds__(256) void k_gather64(const __half* __restrict__ xw,
                                                  __half* __restrict__ agg) {
    const int node = blockIdx.x * 32 + (threadIdx.x >> 3);
    if (node >= N_NODES) return;
    const int f   = (threadIdx.x & 7) << 3;
    int       i   = g_rowoff[node];
    const int end = g_rowoff[node + 1];
    float acc[8] = {0.f, 0.f, 0.f, 0.f, 0.f, 0.f, 0.f, 0.f};

    for (; i + 3 < end; i += 4) {
        const int s0 = __ldg(&g_csrc[i + 0]);
        const int s1 = __ldg(&g_csrc[i + 1]);
        const int s2 = __ldg(&g_csrc[i + 2]);
        const int s3 = __ldg(&g_csrc[i + 3]);
        const uint4 r0 = __ldg((const uint4*)&xw[(size_t)s0 * 64 + f]);
        const uint4 r1 = __ldg((const uint4*)&xw[(size_t)s1 * 64 + f]);
        const uint4 r2 = __ldg((const uint4*)&xw[(size_t)s2 * 64 + f]);
        const uint4 r3 = __ldg((const uint4*)&xw[(size_t)s3 * 64 + f]);
        h8_acc(acc, r0); h8_acc(acc, r1);
        h8_acc(acc, r2); h8_acc(acc, r3);
    }
    for (; i < end; i++) {
        const int s = __ldg(&g_csrc[i]);
        h8_acc(acc, __ldg((const uint4*)&xw[(size_t)s * 64 + f]));
    }

    union { uint4 u; __half2 h[4]; } o;
    o.h[0] = __floats2half2_rn(acc[0], acc[1]);
    o.h[1] = __floats2half2_rn(acc[2], acc[3]);
    o.h[2] = __floats2half2_rn(acc[4], acc[5]);
    o.h[3] = __floats2half2_rn(acc[6], acc[7]);
    *(uint4*)&agg[(size_t)node * 64 + f] = o.u;
}

// 40-wide fp16 gather with fused final epilogue (fp32 output)
__device__ __forceinline__ void h4_acc(float4& acc, uint2 raw) {
    union { uint2 u; __half2 h[2]; } p; p.u = raw;
    const float2 a = __half22float2(p.h[0]);
    const float2 b = __half22float2(p.h[1]);
    acc.x += a.x; acc.y += a.y; acc.z += b.x; acc.w += b.y;
}

__global__ __launch_bounds__(256) void k_gather40(const __half* __restrict__ xw,
                                                  float* __restrict__ out,
                                                  const float* __restrict__ b2) {
    const int node = blockIdx.x * 16 + (threadIdx.x >> 4);
    if (node >= N_NODES) return;
    const int f = (threadIdx.x & 15) << 2;
    if (f >= F_OUT) return;
    int       i   = g_rowoff[node];
    const int end = g_rowoff[node + 1];
    float4 acc = make_float4(0.f, 0.f, 0.f, 0.f);
    for (; i + 3 < end; i += 4) {
        const int s0 = __ldg(&g_csrc[i + 0]);
        const int s1 = __ldg(&g_csrc[i + 1]);
        const int s2 = __ldg(&g_csrc[i + 2]);
        const int s3 = __ldg(&g_csrc[i + 3]);
        h4_acc(acc, __ldg((const uint2*)&xw[(size_t)s0 * F_OUT + f]));
        h4_acc(acc, __ldg((const uint2*)&xw[(size_t)s1 * F_OUT + f]));
        h4_acc(acc, __ldg((const uint2*)&xw[(size_t)s2 * F_OUT + f]));
        h4_acc(acc, __ldg((const uint2*)&xw[(size_t)s3 * F_OUT + f]));
    }
    for (; i < end; i++) {
        const int s = __ldg(&g_csrc[i]);
        h4_acc(acc, __ldg((const uint2*)&xw[(size_t)s * F_OUT + f]));
    }
    const float nd = g_nd[node];
    float4 o;
    o.x = fmaf(acc.x, nd, __ldg(&b2[f + 0]));
    o.y = fmaf(acc.y, nd, __ldg(&b2[f + 1]));
    o.z = fmaf(acc.z, nd, __ldg(&b2[f + 2]));
    o.w = fmaf(acc.w, nd, __ldg(&b2[f + 3]));
    *(float4*)&out[(size_t)node * F_OUT + f] = o;
}

// ---------------- host launch ----------------
extern "C" void kernel_launch(void* const* d_in, const int* in_sizes, int n_in,
                              void* d_out, int out_size) {
    (void)in_sizes; (void)n_in; (void)out_size;
    const float* h   = (const float*)d_in[0];
    const float* W0  = (const float*)d_in[1];
    const float* b0  = (const float*)d_in[2];
    const float* W1  = (const float*)d_in[3];
    const float* b1  = (const float*)d_in[4];
    const float* W2  = (const float*)d_in[5];
    const float* b2  = (const float*)d_in[6];
    const int*   src = (const int*)d_in[7];
    const int*   dst = (const int*)d_in[8];
    float* out = (float*)d_out;

    __half *pXW64, *pXW40, *pAgg;
    cudaGetSymbolAddress((void**)&pXW64, g_xw64);
    cudaGetSymbolAddress((void**)&pXW40, g_xw40);
    cudaGetSymbolAddress((void**)&pAgg,  g_agg);

    static cudaStream_t s2 = []() {
        cudaStream_t s; cudaStreamCreateWithFlags(&s, cudaStreamNonBlocking); return s;
    }();
    static cudaEvent_t evFork = []() {
        cudaEvent_t e; cudaEventCreateWithFlags(&e, cudaEventDisableTiming); return e;
    }();
    static cudaEvent_t evJoin = []() {
        cudaEvent_t e; cudaEventCreateWithFlags(&e, cudaEventDisableTiming); return e;
    }();

    const int nodeBlocks   = (N_NODES + 255) / 256;
    const int edge4Blocks  = (N_EDGES / 4 + 255) / 256;
    const int gemmBlocks   = (N_NODES + 127) / 128;
    const int gath64Blocks = (N_NODES + 31) / 32;
    const int gath40Blocks = (N_NODES + 15) / 16;

    // ---- main: zero degrees, then fork ----
    k_zero_deg<<<(N_NODES / 4 + 255) / 256, 256>>>();
    cudaEventRecord(evFork, 0);

    // ---- side stream: src-degree -> ns -> GEMM0 (ns folded into its epilogue) ----
    cudaStreamWaitEvent(s2, evFork, 0);
    k_deg_src<<<edge4Blocks, 256, 0, s2>>>(src);
    k_ns<<<nodeBlocks, 256, 0, s2>>>();
    k_gemm<F_IN, F_HID, false, true><<<gemmBlocks, 256, 0, s2>>>(h, W0, pXW64, b0);
    cudaEventRecord(evJoin, s2);

    // ---- main: dst histogram + CSR ----
    k_deg_dst<<<edge4Blocks, 256>>>(dst);
    k_scan_block<<<SCAN_NB, SCAN_T>>>();
    k_finalize<<<SCAN_NB, SCAN_T>>>();
    k_fill<<<edge4Blocks, 256>>>(src, dst);

    // ---- join, then the serial back chain (no overlap: gathers are LTS-bound) ----
    cudaStreamWaitEvent(0, evJoin, 0);
    k_gather64<<<gath64Blocks, 256>>>(pXW64, pAgg);

    k_gemm<F_HID, F_HID, true, true><<<gemmBlocks, 256>>>(pAgg, W1, pXW64, b0);
    k_gather64<<<gath64Blocks, 256>>>(pXW64, pAgg);

    k_gemm<F_HID, F_OUT, true, true><<<gemmBlocks, 256>>>(pAgg, W2, pXW40, b1);
    k_gather40<<<gath40Blocks, 256>>>(pXW40, out, b2);
}